// round 1
// baseline (speedup 1.0000x reference)
#include <cuda_runtime.h>
#include <cuda_bf16.h>
#include <cstdint>

// Problem dims
#define M_DIM 16384   // B*S
#define N_DIM 4096    // O
#define K_DIM 4096    // F
#define NCHUNK 4
#define CHUNK_K 1024

// Scratch (device globals: allocation-free rule)
__device__ __nv_bfloat16 g_qx[(size_t)M_DIM * K_DIM];   // quantized x as integer-valued bf16
__device__ __nv_bfloat16 g_qw[(size_t)N_DIM * K_DIM];   // quantized weight as integer-valued bf16
__device__ unsigned g_absmax_bits[8];                    // [0..3]=x chunks, [4]=w

// ---------------------------------------------------------------------------
__global__ void zero_kernel() {
    if (threadIdx.x < 8) g_absmax_bits[threadIdx.x] = 0u;
}

// absmax over src; for x (is_w=0) per input-feature chunk, for w (is_w=1) slot 4.
// stride is a multiple of 4096 elements so each thread stays in one chunk.
__global__ void absmax_kernel(const float* __restrict__ src, int n, int is_w) {
    __shared__ unsigned smax[5];
    if (threadIdx.x < 5) smax[threadIdx.x] = 0u;
    __syncthreads();

    size_t stride = (size_t)gridDim.x * blockDim.x * 4;
    size_t base = ((size_t)blockIdx.x * blockDim.x + threadIdx.x) * 4;
    int c = is_w ? 4 : (int)((base & 4095) >> 10);
    float m = 0.f;
    for (size_t e = base; e < (size_t)n; e += stride) {
        float4 v = *(const float4*)(src + e);
        m = fmaxf(m, fmaxf(fmaxf(fabsf(v.x), fabsf(v.y)),
                           fmaxf(fabsf(v.z), fabsf(v.w))));
    }
    atomicMax(&smax[c], __float_as_uint(m));
    __syncthreads();
    if (threadIdx.x < 5) atomicMax(&g_absmax_bits[threadIdx.x], smax[threadIdx.x]);
}

// ---------------------------------------------------------------------------
__device__ __forceinline__ float quant_scale(int slot) {
    return fmaxf(__uint_as_float(g_absmax_bits[slot]) * (1.0f / 127.0f), 1e-8f);
}

__global__ void quant_x_kernel(const float* __restrict__ x, int n) {
    float inv[NCHUNK];
#pragma unroll
    for (int c = 0; c < NCHUNK; c++) inv[c] = 1.0f / quant_scale(c);

    size_t stride = (size_t)gridDim.x * blockDim.x * 4;
    size_t base = ((size_t)blockIdx.x * blockDim.x + threadIdx.x) * 4;
    for (size_t e = base; e < (size_t)n; e += stride) {
        int c = (int)((e & 4095) >> 10);
        float4 v = *(const float4*)(x + e);
        float q0 = fminf(fmaxf(rintf(v.x * inv[c]), -127.f), 127.f);
        float q1 = fminf(fmaxf(rintf(v.y * inv[c]), -127.f), 127.f);
        float q2 = fminf(fmaxf(rintf(v.z * inv[c]), -127.f), 127.f);
        float q3 = fminf(fmaxf(rintf(v.w * inv[c]), -127.f), 127.f);
        __nv_bfloat162 p0, p1;
        p0.x = __float2bfloat16_rn(q0); p0.y = __float2bfloat16_rn(q1);
        p1.x = __float2bfloat16_rn(q2); p1.y = __float2bfloat16_rn(q3);
        *(__nv_bfloat162*)(&g_qx[e])     = p0;
        *(__nv_bfloat162*)(&g_qx[e + 2]) = p1;
    }
}

__global__ void quant_w_kernel(const float* __restrict__ w, int n) {
    float inv = 1.0f / quant_scale(4);
    size_t stride = (size_t)gridDim.x * blockDim.x * 4;
    size_t base = ((size_t)blockIdx.x * blockDim.x + threadIdx.x) * 4;
    for (size_t e = base; e < (size_t)n; e += stride) {
        float4 v = *(const float4*)(w + e);
        float q0 = fminf(fmaxf(rintf(v.x * inv), -127.f), 127.f);
        float q1 = fminf(fmaxf(rintf(v.y * inv), -127.f), 127.f);
        float q2 = fminf(fmaxf(rintf(v.z * inv), -127.f), 127.f);
        float q3 = fminf(fmaxf(rintf(v.w * inv), -127.f), 127.f);
        __nv_bfloat162 p0, p1;
        p0.x = __float2bfloat16_rn(q0); p0.y = __float2bfloat16_rn(q1);
        p1.x = __float2bfloat16_rn(q2); p1.y = __float2bfloat16_rn(q3);
        *(__nv_bfloat162*)(&g_qw[e])     = p0;
        *(__nv_bfloat162*)(&g_qw[e + 2]) = p1;
    }
}

// ---------------------------------------------------------------------------
// GEMM: out[M,N] = sum_c cs[c] * (qx_c @ qw_c^T) + bias
// 128x128x32 block tile, 8 warps (2x4), warp tile 64x32, mma.sync m16n8k16 bf16.
#define BM 128
#define BN 128
#define BK 32
#define STR 40   // BK + 8 pad (in bf16 elements); 80B row stride, 16B aligned

__device__ __forceinline__ void cp16(void* sdst, const void* gsrc) {
    unsigned sa = (unsigned)__cvta_generic_to_shared(sdst);
    asm volatile("cp.async.cg.shared.global [%0], [%1], 16;\n" :: "r"(sa), "l"(gsrc));
}
#define CP_COMMIT asm volatile("cp.async.commit_group;\n" ::: "memory")
#define CP_WAIT(N) asm volatile("cp.async.wait_group %0;\n" :: "n"(N) : "memory")

__device__ __forceinline__ void mma16816(float* c, const uint32_t* a, const uint32_t* b) {
    asm volatile(
        "mma.sync.aligned.m16n8k16.row.col.f32.bf16.bf16.f32 "
        "{%0,%1,%2,%3}, {%4,%5,%6,%7}, {%8,%9}, {%0,%1,%2,%3};\n"
        : "+f"(c[0]), "+f"(c[1]), "+f"(c[2]), "+f"(c[3])
        : "r"(a[0]), "r"(a[1]), "r"(a[2]), "r"(a[3]), "r"(b[0]), "r"(b[1]));
}

__global__ void __launch_bounds__(256) gemm_kernel(const float* __restrict__ bias,
                                                   float* __restrict__ out) {
    __shared__ __nv_bfloat16 As[2][BM * STR];
    __shared__ __nv_bfloat16 Bs[2][BN * STR];

    const int bn = blockIdx.x, bm = blockIdx.y;
    const int tid = threadIdx.x;
    const int lane = tid & 31, warp = tid >> 5;
    const int g = lane >> 2, t4 = lane & 3;
    const int wm = (warp & 1) * 64;   // warp m-offset within block
    const int wn = (warp >> 1) * 32;  // warp n-offset within block

    // combined per-chunk scales cs[c] = sx_c * sw
    float cs[NCHUNK];
    {
        float sw = quant_scale(4);
#pragma unroll
        for (int c = 0; c < NCHUNK; c++) cs[c] = quant_scale(c) * sw;
    }

    // global->shared load mapping: each thread loads 2x16B for A and B
    const int r = tid >> 1, kc = (tid & 1) * 16;
    const __nv_bfloat16* gA = g_qx + (size_t)(bm * BM + r) * K_DIM + kc;
    const __nv_bfloat16* gB = g_qw + (size_t)(bn * BN + r) * K_DIM + kc;

    auto issue = [&](int stage) {
        int buf = stage & 1;
        int kt = stage * BK;
        cp16(&As[buf][r * STR + kc],     gA + kt);
        cp16(&As[buf][r * STR + kc + 8], gA + kt + 8);
        cp16(&Bs[buf][r * STR + kc],     gB + kt);
        cp16(&Bs[buf][r * STR + kc + 8], gB + kt + 8);
    };

    float acc[4][4][4];
#pragma unroll
    for (int mt = 0; mt < 4; mt++)
#pragma unroll
        for (int nt = 0; nt < 4; nt++)
#pragma unroll
            for (int i = 0; i < 4; i++) acc[mt][nt][i] = 0.f;

    const int NIT = K_DIM / BK;  // 128
    issue(0);
    CP_COMMIT;

    for (int it = 0; it < NIT; ++it) {
        if (it + 1 < NIT) {
            issue(it + 1);
            CP_COMMIT;
            CP_WAIT(1);
        } else {
            CP_WAIT(0);
        }
        __syncthreads();

        const __nv_bfloat16* sa = As[it & 1];
        const __nv_bfloat16* sb = Bs[it & 1];
#pragma unroll
        for (int kk = 0; kk < BK; kk += 16) {
            uint32_t af[4][4], bfr[4][2];
#pragma unroll
            for (int mt = 0; mt < 4; mt++) {
                const __nv_bfloat16* p = sa + (wm + mt * 16 + g) * STR + kk + t4 * 2;
                af[mt][0] = *(const uint32_t*)p;
                af[mt][1] = *(const uint32_t*)(p + 8 * STR);
                af[mt][2] = *(const uint32_t*)(p + 8);
                af[mt][3] = *(const uint32_t*)(p + 8 * STR + 8);
            }
#pragma unroll
            for (int nt = 0; nt < 4; nt++) {
                const __nv_bfloat16* p = sb + (wn + nt * 8 + g) * STR + kk + t4 * 2;
                bfr[nt][0] = *(const uint32_t*)p;
                bfr[nt][1] = *(const uint32_t*)(p + 8);
            }
#pragma unroll
            for (int mt = 0; mt < 4; mt++)
#pragma unroll
                for (int nt = 0; nt < 4; nt++)
                    mma16816(acc[mt][nt], af[mt], bfr[nt]);
        }
        __syncthreads();

        // chunk boundary: rescale accumulator so a single accumulator carries
        // sum_{j<=c} cs[j]*S_j / cs[c]; final result = acc * cs[3].
        if (((it + 1) & 31) == 0 && (it + 1) < NIT) {
            int c = ((it + 1) >> 5) - 1;
            float rt = cs[c] / cs[c + 1];
#pragma unroll
            for (int mt = 0; mt < 4; mt++)
#pragma unroll
                for (int nt = 0; nt < 4; nt++)
#pragma unroll
                    for (int i = 0; i < 4; i++) acc[mt][nt][i] *= rt;
        }
    }

    // epilogue: scale by cs[3], add bias, store fp32
    const float fs = cs[3];
#pragma unroll
    for (int mt = 0; mt < 4; mt++) {
        int row0 = bm * BM + wm + mt * 16 + g;
#pragma unroll
        for (int nt = 0; nt < 4; nt++) {
            int col = bn * BN + wn + nt * 8 + t4 * 2;
            float b0 = bias[col], b1 = bias[col + 1];
            float2 v0 = make_float2(acc[mt][nt][0] * fs + b0, acc[mt][nt][1] * fs + b1);
            float2 v1 = make_float2(acc[mt][nt][2] * fs + b0, acc[mt][nt][3] * fs + b1);
            *(float2*)(out + (size_t)row0 * N_DIM + col) = v0;
            *(float2*)(out + (size_t)(row0 + 8) * N_DIM + col) = v1;
        }
    }
}

// ---------------------------------------------------------------------------
extern "C" void kernel_launch(void* const* d_in, const int* in_sizes, int n_in,
                              void* d_out, int out_size) {
    const float* x = (const float*)d_in[0];      // [4,4096,4096]
    const float* w = (const float*)d_in[1];      // [4096,4096]
    const float* bias = (const float*)d_in[2];   // [4096]
    float* out = (float*)d_out;                  // [4,4096,4096]

    const int nx = M_DIM * K_DIM;   // 67108864
    const int nw = N_DIM * K_DIM;   // 16777216

    zero_kernel<<<1, 32>>>();
    absmax_kernel<<<1024, 256>>>(x, nx, 0);
    absmax_kernel<<<512, 256>>>(w, nw, 1);
    quant_x_kernel<<<8192, 256>>>(x, nx);
    quant_w_kernel<<<2048, 256>>>(w, nw);

    dim3 grid(N_DIM / BN, M_DIM / BM);  // (32, 128)
    gemm_kernel<<<grid, 256>>>(bias, out);
}

// round 3
// speedup vs baseline: 3.0682x; 3.0682x over previous
#include <cuda_runtime.h>
#include <cuda_bf16.h>
#include <cstdint>

#define M_DIM 16384
#define N_DIM 4096
#define K_DIM 4096
#define NCHUNK 4

// tcgen05 available only in an arch-specific (sm_103a/sm_100a) device pass
#if defined(__CUDA_ARCH__) && (defined(__CUDA_ARCH_FEAT_SM103_ALL) || defined(__CUDA_ARCH_FEAT_SM100_ALL) || defined(__CUDA_ARCH_FEAT_SM101_ALL))
#define HAS_TC 1
#else
#define HAS_TC 0
#endif

// Scratch
__device__ __nv_bfloat16 g_qx[(size_t)M_DIM * K_DIM];
__device__ __nv_bfloat16 g_qw[(size_t)N_DIM * K_DIM];
__device__ unsigned g_absmax_bits[8];

// ---------------------------------------------------------------------------
__global__ void zero_kernel() {
    if (threadIdx.x < 8) g_absmax_bits[threadIdx.x] = 0u;
}

__global__ void absmax_kernel(const float* __restrict__ src, int n, int is_w) {
    __shared__ unsigned smax[5];
    if (threadIdx.x < 5) smax[threadIdx.x] = 0u;
    __syncthreads();
    size_t stride = (size_t)gridDim.x * blockDim.x * 4;
    size_t base = ((size_t)blockIdx.x * blockDim.x + threadIdx.x) * 4;
    int c = is_w ? 4 : (int)((base & 4095) >> 10);
    float m = 0.f;
    for (size_t e = base; e < (size_t)n; e += stride) {
        float4 v = *(const float4*)(src + e);
        m = fmaxf(m, fmaxf(fmaxf(fabsf(v.x), fabsf(v.y)),
                           fmaxf(fabsf(v.z), fabsf(v.w))));
    }
    atomicMax(&smax[c], __float_as_uint(m));
    __syncthreads();
    if (threadIdx.x < 5) atomicMax(&g_absmax_bits[threadIdx.x], smax[threadIdx.x]);
}

__device__ __forceinline__ float quant_scale(int slot) {
    return fmaxf(__uint_as_float(g_absmax_bits[slot]) * (1.0f / 127.0f), 1e-8f);
}

__global__ void quant_x_kernel(const float* __restrict__ x, int n) {
    float inv[NCHUNK];
#pragma unroll
    for (int c = 0; c < NCHUNK; c++) inv[c] = 1.0f / quant_scale(c);
    size_t stride = (size_t)gridDim.x * blockDim.x * 4;
    size_t base = ((size_t)blockIdx.x * blockDim.x + threadIdx.x) * 4;
    for (size_t e = base; e < (size_t)n; e += stride) {
        int c = (int)((e & 4095) >> 10);
        float4 v = *(const float4*)(x + e);
        float q0 = fminf(fmaxf(rintf(v.x * inv[c]), -127.f), 127.f);
        float q1 = fminf(fmaxf(rintf(v.y * inv[c]), -127.f), 127.f);
        float q2 = fminf(fmaxf(rintf(v.z * inv[c]), -127.f), 127.f);
        float q3 = fminf(fmaxf(rintf(v.w * inv[c]), -127.f), 127.f);
        __nv_bfloat162 p0, p1;
        p0.x = __float2bfloat16_rn(q0); p0.y = __float2bfloat16_rn(q1);
        p1.x = __float2bfloat16_rn(q2); p1.y = __float2bfloat16_rn(q3);
        *(__nv_bfloat162*)(&g_qx[e])     = p0;
        *(__nv_bfloat162*)(&g_qx[e + 2]) = p1;
    }
}

__global__ void quant_w_kernel(const float* __restrict__ w, int n) {
    float inv = 1.0f / quant_scale(4);
    size_t stride = (size_t)gridDim.x * blockDim.x * 4;
    size_t base = ((size_t)blockIdx.x * blockDim.x + threadIdx.x) * 4;
    for (size_t e = base; e < (size_t)n; e += stride) {
        float4 v = *(const float4*)(w + e);
        float q0 = fminf(fmaxf(rintf(v.x * inv), -127.f), 127.f);
        float q1 = fminf(fmaxf(rintf(v.y * inv), -127.f), 127.f);
        float q2 = fminf(fmaxf(rintf(v.z * inv), -127.f), 127.f);
        float q3 = fminf(fmaxf(rintf(v.w * inv), -127.f), 127.f);
        __nv_bfloat162 p0, p1;
        p0.x = __float2bfloat16_rn(q0); p0.y = __float2bfloat16_rn(q1);
        p1.x = __float2bfloat16_rn(q2); p1.y = __float2bfloat16_rn(q3);
        *(__nv_bfloat162*)(&g_qw[e])     = p0;
        *(__nv_bfloat162*)(&g_qw[e + 2]) = p1;
    }
}

// ===========================================================================
// PATH 1: tcgen05 GEMM (only in arch-specific pass). 128x256 tile, 4 stages.
// ===========================================================================
#define BM 128
#define BN 256
#define SK 64
#define STAGES 4
#define NITER (K_DIM / SK)            // 64
#define A_STAGE_BYTES (BM * 128)      // 16KB
#define B_STAGE_BYTES (BN * 128)      // 32KB
#define STAGE_BYTES (A_STAGE_BYTES + B_STAGE_BYTES)
#define SMEM_STAGE0 1024
#define SMEM_TOTAL (SMEM_STAGE0 + STAGES * STAGE_BYTES)  // 197632

#define MMA_IDESC ((8u << 24) | (32u << 17) | (1u << 10) | (1u << 7) | (1u << 4))

static constexpr uint64_t DESC_BASE_SW128 =
    (uint64_t(2) << 61) | (uint64_t(1) << 46) | (uint64_t(64) << 32) | (uint64_t(1) << 16);

__device__ __forceinline__ uint32_t smem_u32(const void* p) {
    return (uint32_t)__cvta_generic_to_shared(p);
}
__device__ __forceinline__ uint32_t swz(uint32_t o) { return o ^ ((o >> 3) & 0x70); }

__device__ __forceinline__ void cp16(uint32_t sdst, const void* gsrc) {
    asm volatile("cp.async.cg.shared.global [%0], [%1], 16;\n" :: "r"(sdst), "l"(gsrc));
}
#define CPA_COMMIT asm volatile("cp.async.commit_group;\n" ::: "memory")
#define CPA_WAIT(N) asm volatile("cp.async.wait_group %0;\n" :: "n"(N) : "memory")

#define MBAR_INIT(a, n) asm volatile("mbarrier.init.shared.b64 [%0], %1;" :: "r"(a), "r"(n) : "memory")
#define MBAR_INVAL(a)   asm volatile("mbarrier.inval.shared.b64 [%0];" :: "r"(a) : "memory")

__device__ __forceinline__ void mbar_wait(uint32_t addr, uint32_t parity) {
    asm volatile(
        "{\n\t.reg .pred P;\n\t"
        "WAIT_%=:\n\t"
        "mbarrier.try_wait.parity.acquire.cta.shared::cta.b64 P, [%0], %1, 0x989680;\n\t"
        "@P bra.uni DONE_%=;\n\t"
        "bra.uni WAIT_%=;\n\t"
        "DONE_%=:\n\t}"
        :: "r"(addr), "r"(parity) : "memory");
}

#if HAS_TC
#define TC_ALLOC(sp, n)   asm volatile("tcgen05.alloc.cta_group::1.sync.aligned.shared::cta.b32 [%0], %1;" :: "r"(sp), "r"(n) : "memory")
#define TC_DEALLOC(t, n)  asm volatile("tcgen05.dealloc.cta_group::1.sync.aligned.b32 %0, %1;" :: "r"(t), "r"(n))
#define TC_RELINQ()       asm volatile("tcgen05.relinquish_alloc_permit.cta_group::1.sync.aligned;")
#define TC_COMMIT(mb)     asm volatile("tcgen05.commit.cta_group::1.mbarrier::arrive::one.shared::cluster.b64 [%0];" :: "r"(mb) : "memory")
#define TC_WAIT_LD()      asm volatile("tcgen05.wait::ld.sync.aligned;" ::: "memory")
#define TC_WAIT_ST()      asm volatile("tcgen05.wait::st.sync.aligned;" ::: "memory")
#define TC_FENCE_BEFORE() asm volatile("tcgen05.fence::before_thread_sync;" ::: "memory")
#define TC_FENCE_AFTER()  asm volatile("tcgen05.fence::after_thread_sync;" ::: "memory")
#define FENCE_ASYNC()     asm volatile("fence.proxy.async.shared::cta;" ::: "memory")

__device__ __forceinline__ void mma_f16_ss(uint32_t d, uint64_t ad, uint64_t bd,
                                           uint32_t idesc, uint32_t en) {
    asm volatile(
        "{\n\t.reg .pred p;\n\t"
        "setp.ne.u32 p, %4, 0;\n\t"
        "tcgen05.mma.cta_group::1.kind::f16 [%0], %1, %2, %3, {%5,%5,%5,%5}, p;\n\t}"
        :: "r"(d), "l"(ad), "l"(bd), "r"(idesc), "r"(en), "r"(0u) : "memory");
}

#define TC_LD32(r, addr) \
    asm volatile( \
        "tcgen05.ld.sync.aligned.32x32b.x32.b32 " \
        "{%0,%1,%2,%3,%4,%5,%6,%7,%8,%9,%10,%11,%12,%13,%14,%15," \
        "%16,%17,%18,%19,%20,%21,%22,%23,%24,%25,%26,%27,%28,%29,%30,%31}, [%32];" \
        : "=r"((r)[0]),"=r"((r)[1]),"=r"((r)[2]),"=r"((r)[3]),"=r"((r)[4]),"=r"((r)[5]),"=r"((r)[6]),"=r"((r)[7]), \
          "=r"((r)[8]),"=r"((r)[9]),"=r"((r)[10]),"=r"((r)[11]),"=r"((r)[12]),"=r"((r)[13]),"=r"((r)[14]),"=r"((r)[15]), \
          "=r"((r)[16]),"=r"((r)[17]),"=r"((r)[18]),"=r"((r)[19]),"=r"((r)[20]),"=r"((r)[21]),"=r"((r)[22]),"=r"((r)[23]), \
          "=r"((r)[24]),"=r"((r)[25]),"=r"((r)[26]),"=r"((r)[27]),"=r"((r)[28]),"=r"((r)[29]),"=r"((r)[30]),"=r"((r)[31]) \
        : "r"(addr))

#define TC_ST32(addr, r) \
    asm volatile( \
        "tcgen05.st.sync.aligned.32x32b.x32.b32 [%0], " \
        "{%1,%2,%3,%4,%5,%6,%7,%8,%9,%10,%11,%12,%13,%14,%15,%16," \
        "%17,%18,%19,%20,%21,%22,%23,%24,%25,%26,%27,%28,%29,%30,%31,%32};" \
        :: "r"(addr), \
           "r"((r)[0]),"r"((r)[1]),"r"((r)[2]),"r"((r)[3]),"r"((r)[4]),"r"((r)[5]),"r"((r)[6]),"r"((r)[7]), \
           "r"((r)[8]),"r"((r)[9]),"r"((r)[10]),"r"((r)[11]),"r"((r)[12]),"r"((r)[13]),"r"((r)[14]),"r"((r)[15]), \
           "r"((r)[16]),"r"((r)[17]),"r"((r)[18]),"r"((r)[19]),"r"((r)[20]),"r"((r)[21]),"r"((r)[22]),"r"((r)[23]), \
           "r"((r)[24]),"r"((r)[25]),"r"((r)[26]),"r"((r)[27]),"r"((r)[28]),"r"((r)[29]),"r"((r)[30]),"r"((r)[31]) \
        : "memory")
#endif  // HAS_TC

__global__ void __launch_bounds__(256, 1) gemm_tc_kernel(const float* __restrict__ bias,
                                                         float* __restrict__ out) {
#if HAS_TC
    extern __shared__ char smem[];
    const uint32_t sbase = smem_u32(smem);
    const int tid = threadIdx.x;
    const int warp = tid >> 5;
    const int bn = blockIdx.x, bm = blockIdx.y;

    const uint32_t mb_empty = sbase + 16;
    const uint32_t mb_chunk = sbase + 48;
    const uint32_t mb_final = sbase + 56;

    if (tid == 0) {
#pragma unroll
        for (int s = 0; s < STAGES; s++) MBAR_INIT(mb_empty + s * 8, 1);
        MBAR_INIT(mb_chunk, 1);
        MBAR_INIT(mb_final, 1);
    }
    if (warp == 0) { TC_ALLOC(sbase, 512); TC_RELINQ(); }
    __syncthreads();

    uint32_t tmem_base;
    asm volatile("ld.shared.b32 %0, [%1];" : "=r"(tmem_base) : "r"(sbase));

    float cs[NCHUNK];
    {
        float sw = quant_scale(4);
#pragma unroll
        for (int c = 0; c < NCHUNK; c++) cs[c] = quant_scale(c) * sw;
    }

    const __nv_bfloat16* gA = g_qx + (size_t)(bm * BM) * K_DIM;
    const __nv_bfloat16* gB = g_qw + (size_t)(bn * BN) * K_DIM;

    auto produce = [&](int t) {
        const int slot = t & (STAGES - 1);
        const uint32_t abase = sbase + SMEM_STAGE0 + slot * STAGE_BYTES;
        const uint32_t bbase = abase + A_STAGE_BYTES;
        const int kt = t * SK;
#pragma unroll
        for (int j = 0; j < 4; j++) {
            int ch = tid + j * 256;
            int row = ch >> 3, c16 = ch & 7;
            cp16(abase + swz(row * 128 + c16 * 16),
                 gA + (size_t)row * K_DIM + kt + c16 * 8);
        }
#pragma unroll
        for (int j = 0; j < 8; j++) {
            int ch = tid + j * 256;
            int row = ch >> 3, c16 = ch & 7;
            cp16(bbase + swz(row * 128 + c16 * 16),
                 gB + (size_t)row * K_DIM + kt + c16 * 8);
        }
    };

#pragma unroll
    for (int t = 0; t < STAGES - 1; t++) {
        produce(t);
        CPA_COMMIT;
    }

    for (int i = 0; i < NITER; ++i) {
        if (i <= NITER - 3) { CPA_WAIT(2); }
        else if (i == NITER - 2) { CPA_WAIT(1); }
        else { CPA_WAIT(0); }
        __syncthreads();

        if (i == 16 || i == 48) {
            if (tid < 128) {
                mbar_wait(mb_chunk, (i == 16) ? 0u : 1u);
                TC_FENCE_AFTER();
                const float ratio = (i == 16) ? (cs[0] / cs[1]) : (cs[2] / cs[3]);
                const uint32_t accoff = (i == 16) ? 0u : 256u;
                const uint32_t woff = (uint32_t)(tid >> 5) << 21;
#pragma unroll
                for (int nb = 0; nb < 8; nb++) {
                    uint32_t r[32];
                    TC_LD32(r, tmem_base + accoff + nb * 32);
                    TC_WAIT_LD();
#pragma unroll
                    for (int j = 0; j < 32; j++)
                        r[j] = __float_as_uint(__uint_as_float(r[j]) * ratio);
                    TC_ST32(tmem_base + accoff + nb * 32 + woff, r);
                    TC_WAIT_ST();
                }
                TC_FENCE_BEFORE();
            }
            __syncthreads();
        }

        if (tid == 0) {
            FENCE_ASYNC();
            if (i == 16 || i == 48) TC_FENCE_AFTER();
            const int slot = i & (STAGES - 1);
            const uint32_t abase = sbase + SMEM_STAGE0 + slot * STAGE_BYTES;
            const uint64_t ad = DESC_BASE_SW128 | ((uint64_t)(abase >> 4) & 0x3FFF);
            const uint64_t bd = DESC_BASE_SW128 | ((uint64_t)((abase + A_STAGE_BYTES) >> 4) & 0x3FFF);
            const uint32_t d = tmem_base + ((i < 32) ? 0u : 256u);
            const uint32_t en0 = (i == 0 || i == 32) ? 0u : 1u;
#pragma unroll
            for (int k = 0; k < 4; k++)
                mma_f16_ss(d, ad + k * 2, bd + k * 2, MMA_IDESC, (k > 0) ? 1u : en0);
            TC_COMMIT(mb_empty + slot * 8);
            if (i == 15 || i == 47) TC_COMMIT(mb_chunk);
            if (i == NITER - 1) TC_COMMIT(mb_final);
        }

        if (i < NITER - (STAGES - 1)) {
            const int t = i + STAGES - 1;
            // fixed deadlock: slot t has no prior occupant for t < STAGES
            if (t >= STAGES)
                mbar_wait(mb_empty + (t & (STAGES - 1)) * 8, (uint32_t)(((t >> 2) - 1) & 1));
            produce(t);
            CPA_COMMIT;
        }
    }

    mbar_wait(mb_final, 0u);
    TC_FENCE_AFTER();
    if (tid < 128) {
        const float sA = cs[1], sB = cs[3];
        const int row = bm * BM + tid;
        float* orow = out + (size_t)row * N_DIM + bn * BN;
        const float* brow = bias + bn * BN;
#pragma unroll
        for (int nb = 0; nb < 8; nb++) {
            uint32_t a[32], b[32];
            TC_LD32(a, tmem_base + nb * 32);
            TC_LD32(b, tmem_base + 256 + nb * 32);
            TC_WAIT_LD();
#pragma unroll
            for (int j = 0; j < 32; j += 4) {
                float4 bb = *(const float4*)(brow + nb * 32 + j);
                float4 v;
                v.x = __uint_as_float(a[j + 0]) * sA + __uint_as_float(b[j + 0]) * sB + bb.x;
                v.y = __uint_as_float(a[j + 1]) * sA + __uint_as_float(b[j + 1]) * sB + bb.y;
                v.z = __uint_as_float(a[j + 2]) * sA + __uint_as_float(b[j + 2]) * sB + bb.z;
                v.w = __uint_as_float(a[j + 3]) * sA + __uint_as_float(b[j + 3]) * sB + bb.w;
                *(float4*)(orow + nb * 32 + j) = v;
            }
        }
        TC_FENCE_BEFORE();
    }
    __syncthreads();
    if (tid == 0) { MBAR_INVAL(mb_chunk); MBAR_INVAL(mb_final); }
    if (warp == 0) TC_DEALLOC(tmem_base, 512);
#endif  // HAS_TC
}

// ===========================================================================
// PATH 2: fallback mma.sync bf16 GEMM (round-1, known-good). Active only when
// the selected cubin has no tcgen05.
// ===========================================================================
#define FBM 128
#define FBN 128
#define FBK 32
#define FSTR 40

__device__ __forceinline__ void mma16816(float* c, const uint32_t* a, const uint32_t* b) {
    asm volatile(
        "mma.sync.aligned.m16n8k16.row.col.f32.bf16.bf16.f32 "
        "{%0,%1,%2,%3}, {%4,%5,%6,%7}, {%8,%9}, {%0,%1,%2,%3};\n"
        : "+f"(c[0]), "+f"(c[1]), "+f"(c[2]), "+f"(c[3])
        : "r"(a[0]), "r"(a[1]), "r"(a[2]), "r"(a[3]), "r"(b[0]), "r"(b[1]));
}

__global__ void __launch_bounds__(256) gemm_fb_kernel(const float* __restrict__ bias,
                                                      float* __restrict__ out) {
#if !HAS_TC
    __shared__ __nv_bfloat16 As[2][FBM * FSTR];
    __shared__ __nv_bfloat16 Bs[2][FBN * FSTR];

    const int bn = blockIdx.x, bm = blockIdx.y;
    const int tid = threadIdx.x;
    const int lane = tid & 31, warp = tid >> 5;
    const int g = lane >> 2, t4 = lane & 3;
    const int wm = (warp & 1) * 64;
    const int wn = (warp >> 1) * 32;

    float cs[NCHUNK];
    {
        float sw = quant_scale(4);
#pragma unroll
        for (int c = 0; c < NCHUNK; c++) cs[c] = quant_scale(c) * sw;
    }

    const int r = tid >> 1, kc = (tid & 1) * 16;
    const __nv_bfloat16* gA = g_qx + (size_t)(bm * FBM + r) * K_DIM + kc;
    const __nv_bfloat16* gB = g_qw + (size_t)(bn * FBN + r) * K_DIM + kc;

    auto cpa = [&](void* sdst, const void* gsrc) {
        unsigned sa = (unsigned)__cvta_generic_to_shared(sdst);
        asm volatile("cp.async.cg.shared.global [%0], [%1], 16;\n" :: "r"(sa), "l"(gsrc));
    };
    auto issue = [&](int stage) {
        int buf = stage & 1;
        int kt = stage * FBK;
        cpa(&As[buf][r * FSTR + kc],     gA + kt);
        cpa(&As[buf][r * FSTR + kc + 8], gA + kt + 8);
        cpa(&Bs[buf][r * FSTR + kc],     gB + kt);
        cpa(&Bs[buf][r * FSTR + kc + 8], gB + kt + 8);
    };

    float acc[4][4][4];
#pragma unroll
    for (int mt = 0; mt < 4; mt++)
#pragma unroll
        for (int nt = 0; nt < 4; nt++)
#pragma unroll
            for (int i = 0; i < 4; i++) acc[mt][nt][i] = 0.f;

    const int NIT = K_DIM / FBK;  // 128
    issue(0);
    CPA_COMMIT;

    for (int it = 0; it < NIT; ++it) {
        if (it + 1 < NIT) {
            issue(it + 1);
            CPA_COMMIT;
            CPA_WAIT(1);
        } else {
            CPA_WAIT(0);
        }
        __syncthreads();

        const __nv_bfloat16* sa = As[it & 1];
        const __nv_bfloat16* sb = Bs[it & 1];
#pragma unroll
        for (int kk = 0; kk < FBK; kk += 16) {
            uint32_t af[4][4], bfr[4][2];
#pragma unroll
            for (int mt = 0; mt < 4; mt++) {
                const __nv_bfloat16* p = sa + (wm + mt * 16 + g) * FSTR + kk + t4 * 2;
                af[mt][0] = *(const uint32_t*)p;
                af[mt][1] = *(const uint32_t*)(p + 8 * FSTR);
                af[mt][2] = *(const uint32_t*)(p + 8);
                af[mt][3] = *(const uint32_t*)(p + 8 * FSTR + 8);
            }
#pragma unroll
            for (int nt = 0; nt < 4; nt++) {
                const __nv_bfloat16* p = sb + (wn + nt * 8 + g) * FSTR + kk + t4 * 2;
                bfr[nt][0] = *(const uint32_t*)p;
                bfr[nt][1] = *(const uint32_t*)(p + 8);
            }
#pragma unroll
            for (int mt = 0; mt < 4; mt++)
#pragma unroll
                for (int nt = 0; nt < 4; nt++)
                    mma16816(acc[mt][nt], af[mt], bfr[nt]);
        }
        __syncthreads();

        if (((it + 1) & 31) == 0 && (it + 1) < NIT) {
            int c = ((it + 1) >> 5) - 1;
            float rt = cs[c] / cs[c + 1];
#pragma unroll
            for (int mt = 0; mt < 4; mt++)
#pragma unroll
                for (int nt = 0; nt < 4; nt++)
#pragma unroll
                    for (int i = 0; i < 4; i++) acc[mt][nt][i] *= rt;
        }
    }

    const float fs = cs[3];
#pragma unroll
    for (int mt = 0; mt < 4; mt++) {
        int row0 = bm * FBM + wm + mt * 16 + g;
#pragma unroll
        for (int nt = 0; nt < 4; nt++) {
            int col = bn * FBN + wn + nt * 8 + t4 * 2;
            float b0 = bias[col], b1 = bias[col + 1];
            float2 v0 = make_float2(acc[mt][nt][0] * fs + b0, acc[mt][nt][1] * fs + b1);
            float2 v1 = make_float2(acc[mt][nt][2] * fs + b0, acc[mt][nt][3] * fs + b1);
            *(float2*)(out + (size_t)row0 * N_DIM + col) = v0;
            *(float2*)(out + (size_t)(row0 + 8) * N_DIM + col) = v1;
        }
    }
#endif  // !HAS_TC
}

// ---------------------------------------------------------------------------
extern "C" void kernel_launch(void* const* d_in, const int* in_sizes, int n_in,
                              void* d_out, int out_size) {
    const float* x = (const float*)d_in[0];
    const float* w = (const float*)d_in[1];
    const float* bias = (const float*)d_in[2];
    float* out = (float*)d_out;

    const int nx = M_DIM * K_DIM;
    const int nw = N_DIM * K_DIM;

    zero_kernel<<<1, 32>>>();
    absmax_kernel<<<1024, 256>>>(x, nx, 0);
    absmax_kernel<<<512, 256>>>(w, nw, 1);
    quant_x_kernel<<<8192, 256>>>(x, nx);
    quant_w_kernel<<<2048, 256>>>(w, nw);

    cudaFuncSetAttribute(gemm_tc_kernel,
                         cudaFuncAttributeMaxDynamicSharedMemorySize, SMEM_TOTAL);
    dim3 gtc(N_DIM / BN, M_DIM / BM);   // (16, 128)
    gemm_tc_kernel<<<gtc, 256, SMEM_TOTAL>>>(bias, out);

    dim3 gfb(N_DIM / FBN, M_DIM / FBM); // (32, 128)
    gemm_fb_kernel<<<gfb, 256>>>(bias, out);
}